// round 12
// baseline (speedup 1.0000x reference)
#include <cuda_runtime.h>
#include <cstdint>

#define NNODES 100000
#define DF 256
#define BQ 1024
#define S0 25
#define S1 10
#define N1 (BQ * (1 + S1))   /* 11264 */
#define KDIM 512
#define BK 32
#define NCH (KDIM / BK)      /* 16 */
#define ASTR 36              /* BK + 4 */
#define A2STR 132            /* 128 + 4 (gemm2 single-stage) */
#define NTILE (N1 / 128)     /* 88 */

// ---------------- scratch (__device__ globals; no allocs allowed) ----------
__device__ float g_X1[(size_t)N1 * KDIM];
__device__ float g_H1[(size_t)N1 * DF];
__device__ float g_X2[(size_t)BQ * KDIM];
__device__ float g_W0r[(size_t)DF * KDIM];
__device__ float g_W1r[(size_t)DF * KDIM];
__device__ float g_P[4][(size_t)BQ * DF];
__device__ unsigned g_cnt[96];   // [0]=prep arrivals, [1+t]=tile t arrivals

// ---------------- small PTX helpers ---------------------------------------
__device__ __forceinline__ uint32_t smem_u32(const void* p) {
    uint32_t a;
    asm("{ .reg .u64 t; cvta.to.shared.u64 t, %1; cvt.u32.u64 %0, t; }" : "=r"(a) : "l"(p));
    return a;
}
__device__ __forceinline__ void cpa16(uint32_t dst, const void* src) {
    asm volatile("cp.async.cg.shared.global [%0], [%1], 16;" :: "r"(dst), "l"(src));
}
#define CP_COMMIT() asm volatile("cp.async.commit_group;" ::: "memory")
#define CP_WAIT(n)  asm volatile("cp.async.wait_group %0;" :: "n"(n) : "memory")

__device__ __forceinline__ float tf32r(float f) {
    uint32_t u;
    asm("cvt.rna.tf32.f32 %0, %1;" : "=r"(u) : "f"(f));
    return __uint_as_float(u);
}
__device__ __forceinline__ float4 tf32r4(float4 v) {
    return make_float4(tf32r(v.x), tf32r(v.y), tf32r(v.z), tf32r(v.w));
}
__device__ __forceinline__ void mma_tf32(float* d, const uint32_t* a, const uint32_t* b) {
    asm volatile(
        "mma.sync.aligned.m16n8k8.row.col.f32.tf32.tf32.f32 "
        "{%0,%1,%2,%3},{%4,%5,%6,%7},{%8,%9},{%0,%1,%2,%3};"
        : "+f"(d[0]), "+f"(d[1]), "+f"(d[2]), "+f"(d[3])
        : "r"(a[0]), "r"(a[1]), "r"(a[2]), "r"(a[3]), "r"(b[0]), "r"(b[1]));
}

// ---------------------------------------------------------------------------
// gather1 + W-prep (SMALL smem -> high occupancy). Signals per-tile counters.
//   blocks [0,512): tf32-round W0,W1; bump g_cnt[0]
//   blocks 512+b  : gather 4 rows (r=b*4..) of X1; bump g_cnt[1 + b/32]
// ---------------------------------------------------------------------------
__global__ void __launch_bounds__(256) prep_gather1(
    const float4* __restrict__ F, const float* __restrict__ W0,
    const float* __restrict__ W1, const int* __restrict__ nodes2,
    const int* __restrict__ neigh2, const int* __restrict__ neigh1) {
    const int tid = threadIdx.x;
    if (blockIdx.x < 512) {
        int i = blockIdx.x * 256 + tid;
        g_W0r[i] = tf32r(W0[i]);
        g_W1r[i] = tf32r(W1[i]);
        __threadfence();
        __syncthreads();
        if (tid == 0) atomicAdd(&g_cnt[0], 1u);
        return;
    }
    const int b = blockIdx.x - 512;
    const int g = tid >> 6, c = tid & 63;
    const int r = b * 4 + g;
    __shared__ int sidx[4][S0 + 1];
    if (c < S0) sidx[g][c] = neigh1[(size_t)r * S0 + c];
    else if (c == S0) sidx[g][S0] = (r < BQ) ? nodes2[r] : neigh2[r - BQ];
    __syncthreads();

    float4* X1v = (float4*)g_X1;
    X1v[(size_t)r * 128 + c] = tf32r4(F[(size_t)sidx[g][S0] * 64 + c]);

    float4 s = make_float4(0.f, 0.f, 0.f, 0.f);
#pragma unroll
    for (int j = 0; j < S0; j++) {
        float4 v = F[(size_t)sidx[g][j] * 64 + c];
        s.x += v.x; s.y += v.y; s.z += v.z; s.w += v.w;
    }
    const float is = 1.0f / S0;
    s.x *= is; s.y *= is; s.z *= is; s.w *= is;
    X1v[(size_t)r * 128 + 64 + c] = tf32r4(s);

    __threadfence();
    __syncthreads();
    if (tid == 0) atomicAdd(&g_cnt[1 + b / 32], 1u);
}

// ---------------------------------------------------------------------------
// GEMM1 (runs CONCURRENTLY with prep_gather1 on a forked stream).
// Spins until W prep + its tile's 32 gather blocks arrive, then R7 pipeline:
// 128x256x512, 3-stage cp.async ring, one barrier per chunk,
// bias+ReLU+L2norm epilogue from registers.
// ---------------------------------------------------------------------------
__global__ void __launch_bounds__(256, 1)
gemm1_kernel(const float* __restrict__ bias, float* __restrict__ out) {
    constexpr int BM = 128, BN = 256, MT = 4, NT = 8;

    extern __shared__ float sm[];
    float* As = sm;                    // [3][BM][ASTR]
    float* Bs = sm + 3 * BM * ASTR;    // [3][BN][ASTR]
    float* ssq_s = sm;                 // reused post-compute [128][4]
    float* inv_s = sm + 512;           // [128]

    const int tid  = threadIdx.x;
    const int t    = blockIdx.x;

    if (tid == 0) {
        while (atomicAdd(&g_cnt[0], 0u) < 512u) __nanosleep(128);
        while (atomicAdd(&g_cnt[1 + t], 0u) < 32u) __nanosleep(128);
        __threadfence();
    }
    __syncthreads();

    const float* X = g_X1;
    const float* W = g_W0r;
    const int wid  = tid >> 5;
    const int lane = tid & 31;
    const int wrow = wid >> 2;
    const int wcol = wid & 3;
    const int rb   = t * BM;
    const int lq   = lane >> 2;
    const int lr   = lane & 3;

    const uint32_t as_b = smem_u32(As);
    const uint32_t bs_b = smem_u32(Bs);

    float acc[MT][NT][4];
#pragma unroll
    for (int i = 0; i < MT; i++)
#pragma unroll
        for (int j = 0; j < NT; j++)
#pragma unroll
            for (int q = 0; q < 4; q++) acc[i][j][q] = 0.f;

    auto stage = [&](int ch, int buf) {
        const float* xb = X + (size_t)rb * KDIM + ch * BK;
        const float* wb = W + ch * BK;
#pragma unroll
        for (int i = tid; i < BM * 8; i += 256) {
            int r = i >> 3, q = i & 7;
            cpa16(as_b + ((buf * BM + r) * ASTR + q * 4) * 4, xb + (size_t)r * KDIM + q * 4);
        }
#pragma unroll
        for (int i = tid; i < BN * 8; i += 256) {
            int n = i >> 3, q = i & 7;
            cpa16(bs_b + ((buf * BN + n) * ASTR + q * 4) * 4, wb + (size_t)n * KDIM + q * 4);
        }
    };

    auto compute = [&](int buf) {
#pragma unroll
        for (int ks = 0; ks < 4; ks++) {
            const int k0 = ks * 8;
            uint32_t af[MT][4];
#pragma unroll
            for (int mt = 0; mt < MT; mt++) {
                const uint32_t* ap = (const uint32_t*)(As
                    + (size_t)(buf * BM + wrow * 64 + mt * 16 + lq) * ASTR + k0 + lr);
                af[mt][0] = ap[0];
                af[mt][1] = ap[8 * ASTR];
                af[mt][2] = ap[4];
                af[mt][3] = ap[8 * ASTR + 4];
            }
            uint32_t bf[NT][2];
#pragma unroll
            for (int nt = 0; nt < NT; nt++) {
                const uint32_t* bp = (const uint32_t*)(Bs
                    + (size_t)(buf * BN + wcol * 64 + nt * 8 + lq) * ASTR + k0 + lr);
                bf[nt][0] = bp[0];
                bf[nt][1] = bp[4];
            }
#pragma unroll
            for (int mt = 0; mt < MT; mt++)
#pragma unroll
                for (int nt = 0; nt < NT; nt++)
                    mma_tf32(acc[mt][nt], af[mt], bf[nt]);
        }
    };

    stage(0, 0); CP_COMMIT();
    stage(1, 1); CP_COMMIT();
    for (int ch = 0; ch < NCH; ch++) {
        if (ch + 1 < NCH) CP_WAIT(1); else CP_WAIT(0);
        __syncthreads();
        if (ch + 2 < NCH) { stage(ch + 2, (ch + 2) % 3); CP_COMMIT(); }
        compute(ch % 3);
    }
    __syncthreads();

#pragma unroll
    for (int mt = 0; mt < MT; mt++) {
        float s0 = 0.f, s1 = 0.f;
#pragma unroll
        for (int nt = 0; nt < NT; nt++) {
            const int col = wcol * 64 + nt * 8 + 2 * lr;
            const float b0 = __ldg(&bias[col]);
            const float b1 = __ldg(&bias[col + 1]);
            float v0 = fmaxf(acc[mt][nt][0] + b0, 0.f);
            float v1 = fmaxf(acc[mt][nt][1] + b1, 0.f);
            float v2 = fmaxf(acc[mt][nt][2] + b0, 0.f);
            float v3 = fmaxf(acc[mt][nt][3] + b1, 0.f);
            acc[mt][nt][0] = v0; acc[mt][nt][1] = v1;
            acc[mt][nt][2] = v2; acc[mt][nt][3] = v3;
            s0 += v0 * v0 + v1 * v1;
            s1 += v2 * v2 + v3 * v3;
        }
        s0 += __shfl_xor_sync(0xffffffffu, s0, 1);
        s0 += __shfl_xor_sync(0xffffffffu, s0, 2);
        s1 += __shfl_xor_sync(0xffffffffu, s1, 1);
        s1 += __shfl_xor_sync(0xffffffffu, s1, 2);
        if (lr == 0) {
            ssq_s[(wrow * 64 + mt * 16 + lq) * 4 + wcol] = s0;
            ssq_s[(wrow * 64 + mt * 16 + lq + 8) * 4 + wcol] = s1;
        }
    }
    __syncthreads();
    if (tid < 128) {
        float v = ssq_s[tid * 4] + ssq_s[tid * 4 + 1] + ssq_s[tid * 4 + 2] + ssq_s[tid * 4 + 3];
        inv_s[tid] = (v > 0.f) ? rsqrtf(v) : 1.0f;
    }
    __syncthreads();

#pragma unroll
    for (int mt = 0; mt < MT; mt++) {
        const int r0 = wrow * 64 + mt * 16 + lq;
        const float i0 = inv_s[r0], i1 = inv_s[r0 + 8];
#pragma unroll
        for (int nt = 0; nt < NT; nt++) {
            const int col = wcol * 64 + nt * 8 + 2 * lr;
            *(float2*)(out + (size_t)(rb + r0) * DF + col) =
                make_float2(acc[mt][nt][0] * i0, acc[mt][nt][1] * i0);
            *(float2*)(out + (size_t)(rb + r0 + 8) * DF + col) =
                make_float2(acc[mt][nt][2] * i1, acc[mt][nt][3] * i1);
        }
    }
}

// ---------------------------------------------------------------------------
// Gather 2: X2 = tf32round([H1[r] | mean_{10} H1[...]])  — 8 rows / 512 thr
// ---------------------------------------------------------------------------
__global__ void __launch_bounds__(512) gather2_kernel() {
    const int g = threadIdx.x >> 6, c = threadIdx.x & 63;
    const int r = blockIdx.x * 8 + g;
    const float4* H = (const float4*)g_H1;
    float4* X2v = (float4*)g_X2;
    X2v[(size_t)r * 128 + c] = tf32r4(H[(size_t)r * 64 + c]);
    float4 s = make_float4(0.f, 0.f, 0.f, 0.f);
#pragma unroll
    for (int j = 0; j < S1; j++) {
        float4 v = H[(size_t)(BQ + r * S1 + j) * 64 + c];
        s.x += v.x; s.y += v.y; s.z += v.z; s.w += v.w;
    }
    const float is = 1.0f / S1;
    s.x *= is; s.y *= is; s.z *= is; s.w *= is;
    X2v[(size_t)r * 128 + 64 + c] = tf32r4(s);
}

// ---------------------------------------------------------------------------
// GEMM2 split-K, SINGLE stage: 32 rows x 256 cols x K=128 per CTA.
// Whole slice staged via one cp.async group -> one latency exposure.
// ---------------------------------------------------------------------------
__global__ void __launch_bounds__(256, 1)
gemm2_splitk(const float* __restrict__ X, const float* __restrict__ W) {
    constexpr int BM = 32, BN = 256, NT = 8;

    extern __shared__ float sm[];
    float* As = sm;                    // [BM][A2STR]
    float* Bs = sm + BM * A2STR;       // [BN][A2STR]

    const int tid  = threadIdx.x;
    const int wid  = tid >> 5;
    const int lane = tid & 31;
    const int wrow = wid >> 2;
    const int wcol = wid & 3;
    const int rb   = blockIdx.x * BM;
    const int kbase = blockIdx.y * 128;
    const int lq   = lane >> 2;
    const int lr   = lane & 3;

    const uint32_t as_b = smem_u32(As);
    const uint32_t bs_b = smem_u32(Bs);

    // stage everything: A = 32x32 float4, B = 256x32 float4
#pragma unroll
    for (int i = tid; i < BM * 32; i += 256) {
        int r = i >> 5, q = i & 31;
        cpa16(as_b + (uint32_t)(r * A2STR + q * 4) * 4,
              X + (size_t)(rb + r) * KDIM + kbase + q * 4);
    }
#pragma unroll
    for (int i = tid; i < BN * 32; i += 256) {
        int n = i >> 5, q = i & 31;
        cpa16(bs_b + (uint32_t)(n * A2STR + q * 4) * 4,
              W + (size_t)n * KDIM + kbase + q * 4);
    }
    CP_COMMIT();

    float acc[NT][4];
#pragma unroll
    for (int j = 0; j < NT; j++)
#pragma unroll
        for (int q = 0; q < 4; q++) acc[j][q] = 0.f;

    CP_WAIT(0);
    __syncthreads();

#pragma unroll
    for (int ks = 0; ks < 16; ks++) {
        const int k0 = ks * 8;
        uint32_t af[4];
        {
            const uint32_t* ap = (const uint32_t*)(As
                + (size_t)(wrow * 16 + lq) * A2STR + k0 + lr);
            af[0] = ap[0];
            af[1] = ap[8 * A2STR];
            af[2] = ap[4];
            af[3] = ap[8 * A2STR + 4];
        }
        uint32_t bf[NT][2];
#pragma unroll
        for (int nt = 0; nt < NT; nt++) {
            const uint32_t* bp = (const uint32_t*)(Bs
                + (size_t)(wcol * 64 + nt * 8 + lq) * A2STR + k0 + lr);
            bf[nt][0] = bp[0];
            bf[nt][1] = bp[4];
        }
#pragma unroll
        for (int nt = 0; nt < NT; nt++)
            mma_tf32(acc[nt], af, bf[nt]);
    }

    float* P = g_P[blockIdx.y];
    const int r0 = wrow * 16 + lq;
#pragma unroll
    for (int nt = 0; nt < NT; nt++) {
        const int col = wcol * 64 + nt * 8 + 2 * lr;
        *(float2*)(P + (size_t)(rb + r0) * DF + col)     = make_float2(acc[nt][0], acc[nt][1]);
        *(float2*)(P + (size_t)(rb + r0 + 8) * DF + col) = make_float2(acc[nt][2], acc[nt][3]);
    }
}

// ---------------------------------------------------------------------------
// Combine: sum 4 partials + bias + relu + L2 norm -> final output.
// ---------------------------------------------------------------------------
__global__ void __launch_bounds__(512) combine_kernel(const float* __restrict__ bias,
                                                      float* __restrict__ out) {
    const int wid = threadIdx.x >> 5, lane = threadIdx.x & 31;
    const int row = blockIdx.x * 16 + wid;

    const float4* P0 = (const float4*)(g_P[0] + (size_t)row * DF);
    const float4* P1 = (const float4*)(g_P[1] + (size_t)row * DF);
    const float4* P2 = (const float4*)(g_P[2] + (size_t)row * DF);
    const float4* P3 = (const float4*)(g_P[3] + (size_t)row * DF);
    const float4* Bv = (const float4*)bias;

    float4 v[2];
    float ssq = 0.f;
#pragma unroll
    for (int t = 0; t < 2; t++) {
        const int idx = lane + t * 32;
        float4 a = P0[idx], b = P1[idx], c = P2[idx], d = P3[idx], e = Bv[idx];
        float4 r;
        r.x = fmaxf(a.x + b.x + c.x + d.x + e.x, 0.f);
        r.y = fmaxf(a.y + b.y + c.y + d.y + e.y, 0.f);
        r.z = fmaxf(a.z + b.z + c.z + d.z + e.z, 0.f);
        r.w = fmaxf(a.w + b.w + c.w + d.w + e.w, 0.f);
        ssq += r.x * r.x + r.y * r.y + r.z * r.z + r.w * r.w;
        v[t] = r;
    }
#pragma unroll
    for (int o = 16; o > 0; o >>= 1)
        ssq += __shfl_xor_sync(0xffffffffu, ssq, o);
    const float inv = (ssq > 0.f) ? rsqrtf(ssq) : 1.0f;

    float4* dst = (float4*)(out + (size_t)row * DF);
#pragma unroll
    for (int t = 0; t < 2; t++) {
        float4 r = v[t];
        r.x *= inv; r.y *= inv; r.z *= inv; r.w *= inv;
        dst[lane + t * 32] = r;
    }
}

// ---------------------------------------------------------------------------
extern "C" void kernel_launch(void* const* d_in, const int* in_sizes, int n_in,
                              void* d_out, int out_size) {
    const float* features = (const float*)d_in[0];
    const float* W0       = (const float*)d_in[1];
    const float* b0       = (const float*)d_in[2];
    const float* W1       = (const float*)d_in[3];
    const float* b1       = (const float*)d_in[4];
    const int*   nodes2   = (const int*)d_in[5];
    const int*   neigh2   = (const int*)d_in[6];
    const int*   neigh1   = (const int*)d_in[7];
    float*       outp     = (float*)d_out;

    float *h1, *x2, *w1r;
    void* cntp;
    cudaGetSymbolAddress((void**)&h1, g_H1);
    cudaGetSymbolAddress((void**)&x2, g_X2);
    cudaGetSymbolAddress((void**)&w1r, g_W1r);
    cudaGetSymbolAddress(&cntp, g_cnt);

    constexpr int SM1 = 3 * (128 + 256) * ASTR * 4;    // 165888
    constexpr int SM2 = (32 + 256) * A2STR * 4;        // 152064

    static bool init_done = false;
    static cudaStream_t s1;
    static cudaEvent_t evFork, evJoin;
    if (!init_done) {
        cudaFuncSetAttribute((const void*)gemm1_kernel,
                             cudaFuncAttributeMaxDynamicSharedMemorySize, SM1);
        cudaFuncSetAttribute((const void*)gemm2_splitk,
                             cudaFuncAttributeMaxDynamicSharedMemorySize, SM2);
        cudaStreamCreateWithFlags(&s1, cudaStreamNonBlocking);
        cudaEventCreateWithFlags(&evFork, cudaEventDisableTiming);
        cudaEventCreateWithFlags(&evJoin, cudaEventDisableTiming);
        init_done = true;
    }

    // reset progress counters, then fork: gather (stream 0) || gemm1 (s1)
    cudaMemsetAsync(cntp, 0, sizeof(g_cnt), 0);
    cudaEventRecord(evFork, 0);
    cudaStreamWaitEvent(s1, evFork, 0);

    prep_gather1<<<512 + N1 / 4, 256>>>((const float4*)features, W0, W1,
                                        nodes2, neigh2, neigh1);
    gemm1_kernel<<<NTILE, 256, SM1, s1>>>(b0, h1);

    cudaEventRecord(evJoin, s1);
    cudaStreamWaitEvent(0, evJoin, 0);

    gather2_kernel<<<BQ / 8, 512>>>();
    gemm2_splitk<<<dim3(BQ / 32, 4), 256, SM2>>>(x2, w1r);
    combine_kernel<<<BQ / 16, 512>>>(b1, outp);
}

// round 14
// speedup vs baseline: 1.0668x; 1.0668x over previous
#include <cuda_runtime.h>
#include <cstdint>

#define NNODES 100000
#define DF 256
#define BQ 1024
#define S0 25
#define S1 10
#define N1 (BQ * (1 + S1))   /* 11264 */
#define KDIM 512
#define BK 32
#define NCH (KDIM / BK)      /* 16 */
#define ASTR 36              /* BK + 4 */
#define A2STR 132            /* 128 + 4 (gemm2 single-stage) */
#define NTILE (N1 / 128)     /* 88 */

// ---------------- scratch (__device__ globals; no allocs allowed) ----------
__device__ float g_X1[(size_t)N1 * KDIM];
__device__ float g_H1[(size_t)N1 * DF];
__device__ float g_X2[(size_t)BQ * KDIM];
__device__ float g_W0r[(size_t)DF * KDIM];
__device__ float g_W1r[(size_t)DF * KDIM];
__device__ float g_P[4][(size_t)BQ * DF];

// ---------------- small PTX helpers ---------------------------------------
__device__ __forceinline__ uint32_t smem_u32(const void* p) {
    uint32_t a;
    asm("{ .reg .u64 t; cvta.to.shared.u64 t, %1; cvt.u32.u64 %0, t; }" : "=r"(a) : "l"(p));
    return a;
}
__device__ __forceinline__ void cpa16(uint32_t dst, const void* src) {
    asm volatile("cp.async.cg.shared.global [%0], [%1], 16;" :: "r"(dst), "l"(src));
}
#define CP_COMMIT() asm volatile("cp.async.commit_group;" ::: "memory")
#define CP_WAIT(n)  asm volatile("cp.async.wait_group %0;" :: "n"(n) : "memory")

__device__ __forceinline__ float tf32r(float f) {
    uint32_t u;
    asm("cvt.rna.tf32.f32 %0, %1;" : "=r"(u) : "f"(f));
    return __uint_as_float(u);
}
__device__ __forceinline__ float4 tf32r4(float4 v) {
    return make_float4(tf32r(v.x), tf32r(v.y), tf32r(v.z), tf32r(v.w));
}
__device__ __forceinline__ void mma_tf32(float* d, const uint32_t* a, const uint32_t* b) {
    asm volatile(
        "mma.sync.aligned.m16n8k8.row.col.f32.tf32.tf32.f32 "
        "{%0,%1,%2,%3},{%4,%5,%6,%7},{%8,%9},{%0,%1,%2,%3};"
        : "+f"(d[0]), "+f"(d[1]), "+f"(d[2]), "+f"(d[3])
        : "r"(a[0]), "r"(a[1]), "r"(a[2]), "r"(a[3]), "r"(b[0]), "r"(b[1]));
}

// ---------------------------------------------------------------------------
// Kernel 1: W-prep (blocks 0..511) + gather1 (blocks 512..).
// gather: X1[r] = tf32round([feat[self] | mean_{25} feat[neigh]]), 4 rows/blk
// ---------------------------------------------------------------------------
__global__ void __launch_bounds__(256) prep_gather1(
    const float4* __restrict__ F, const float* __restrict__ W0,
    const float* __restrict__ W1, const int* __restrict__ nodes2,
    const int* __restrict__ neigh2, const int* __restrict__ neigh1) {
    if (blockIdx.x < 512) {
        int i = blockIdx.x * 256 + threadIdx.x;
        g_W0r[i] = tf32r(W0[i]);
        g_W1r[i] = tf32r(W1[i]);
        return;
    }
    const int b = blockIdx.x - 512;
    const int g = threadIdx.x >> 6, c = threadIdx.x & 63;
    const int r = b * 4 + g;
    __shared__ int sidx[4][S0 + 1];
    if (c < S0) sidx[g][c] = neigh1[(size_t)r * S0 + c];
    else if (c == S0) sidx[g][S0] = (r < BQ) ? nodes2[r] : neigh2[r - BQ];
    __syncthreads();

    float4* X1v = (float4*)g_X1;
    X1v[(size_t)r * 128 + c] = tf32r4(F[(size_t)sidx[g][S0] * 64 + c]);

    float4 s = make_float4(0.f, 0.f, 0.f, 0.f);
#pragma unroll
    for (int j = 0; j < S0; j++) {
        float4 v = F[(size_t)sidx[g][j] * 64 + c];
        s.x += v.x; s.y += v.y; s.z += v.z; s.w += v.w;
    }
    const float is = 1.0f / S0;
    s.x *= is; s.y *= is; s.z *= is; s.w *= is;
    X1v[(size_t)r * 128 + 64 + c] = tf32r4(s);
}

// ---------------------------------------------------------------------------
// GEMM1: 128x256x512 per CTA, tf32 mma.sync, pre-rounded inputs.
// 512 threads, 4x4 warps, warp tile 32x64 (MT=2, NT=8) -> 4 warps/SMSP.
// 3-stage cp.async ring, ONE __syncthreads per chunk.
// ---------------------------------------------------------------------------
__global__ void __launch_bounds__(512, 1)
gemm1_kernel(const float* __restrict__ X, const float* __restrict__ W,
             const float* __restrict__ bias, float* __restrict__ out) {
    constexpr int BM = 128, BN = 256, MT = 2, NT = 8;

    extern __shared__ float sm[];
    float* As = sm;                    // [3][BM][ASTR]
    float* Bs = sm + 3 * BM * ASTR;    // [3][BN][ASTR]
    float* ssq_s = sm;                 // reused post-compute: [128][4]
    float* inv_s = sm + 512;           // [128]

    const int tid  = threadIdx.x;
    const int wid  = tid >> 5;
    const int lane = tid & 31;
    const int wrow = wid >> 2;         // 0..3
    const int wcol = wid & 3;          // 0..3
    const int rb   = blockIdx.x * BM;
    const int lq   = lane >> 2;
    const int lr   = lane & 3;

    const uint32_t as_b = smem_u32(As);
    const uint32_t bs_b = smem_u32(Bs);

    float acc[MT][NT][4];
#pragma unroll
    for (int i = 0; i < MT; i++)
#pragma unroll
        for (int j = 0; j < NT; j++)
#pragma unroll
            for (int q = 0; q < 4; q++) acc[i][j][q] = 0.f;

    auto stage = [&](int ch, int buf) {
        const float* xb = X + (size_t)rb * KDIM + ch * BK;
        const float* wb = W + ch * BK;
#pragma unroll
        for (int i = tid; i < BM * 8; i += 512) {
            int r = i >> 3, q = i & 7;
            cpa16(as_b + ((buf * BM + r) * ASTR + q * 4) * 4, xb + (size_t)r * KDIM + q * 4);
        }
#pragma unroll
        for (int i = tid; i < BN * 8; i += 512) {
            int n = i >> 3, q = i & 7;
            cpa16(bs_b + ((buf * BN + n) * ASTR + q * 4) * 4, wb + (size_t)n * KDIM + q * 4);
        }
    };

    auto compute = [&](int buf) {
#pragma unroll
        for (int ks = 0; ks < 4; ks++) {
            const int k0 = ks * 8;
            uint32_t af[MT][4];
#pragma unroll
            for (int mt = 0; mt < MT; mt++) {
                const uint32_t* ap = (const uint32_t*)(As
                    + (size_t)(buf * BM + wrow * 32 + mt * 16 + lq) * ASTR + k0 + lr);
                af[mt][0] = ap[0];
                af[mt][1] = ap[8 * ASTR];
                af[mt][2] = ap[4];
                af[mt][3] = ap[8 * ASTR + 4];
            }
            uint32_t bf[NT][2];
#pragma unroll
            for (int nt = 0; nt < NT; nt++) {
                const uint32_t* bp = (const uint32_t*)(Bs
                    + (size_t)(buf * BN + wcol * 64 + nt * 8 + lq) * ASTR + k0 + lr);
                bf[nt][0] = bp[0];
                bf[nt][1] = bp[4];
            }
#pragma unroll
            for (int mt = 0; mt < MT; mt++)
#pragma unroll
                for (int nt = 0; nt < NT; nt++)
                    mma_tf32(acc[mt][nt], af[mt], bf[nt]);
        }
    };

    stage(0, 0); CP_COMMIT();
    stage(1, 1); CP_COMMIT();
    for (int ch = 0; ch < NCH; ch++) {
        if (ch + 1 < NCH) CP_WAIT(1); else CP_WAIT(0);
        __syncthreads();
        if (ch + 2 < NCH) { stage(ch + 2, (ch + 2) % 3); CP_COMMIT(); }
        compute(ch % 3);
    }
    __syncthreads();   // before smem reuse in epilogue

    // ---- epilogue: bias + relu, row ssq, normalize, store ----
#pragma unroll
    for (int mt = 0; mt < MT; mt++) {
        float s0 = 0.f, s1 = 0.f;
#pragma unroll
        for (int nt = 0; nt < NT; nt++) {
            const int col = wcol * 64 + nt * 8 + 2 * lr;
            const float b0 = __ldg(&bias[col]);
            const float b1 = __ldg(&bias[col + 1]);
            float v0 = fmaxf(acc[mt][nt][0] + b0, 0.f);
            float v1 = fmaxf(acc[mt][nt][1] + b1, 0.f);
            float v2 = fmaxf(acc[mt][nt][2] + b0, 0.f);
            float v3 = fmaxf(acc[mt][nt][3] + b1, 0.f);
            acc[mt][nt][0] = v0; acc[mt][nt][1] = v1;
            acc[mt][nt][2] = v2; acc[mt][nt][3] = v3;
            s0 += v0 * v0 + v1 * v1;
            s1 += v2 * v2 + v3 * v3;
        }
        s0 += __shfl_xor_sync(0xffffffffu, s0, 1);
        s0 += __shfl_xor_sync(0xffffffffu, s0, 2);
        s1 += __shfl_xor_sync(0xffffffffu, s1, 1);
        s1 += __shfl_xor_sync(0xffffffffu, s1, 2);
        if (lr == 0) {
            ssq_s[(wrow * 32 + mt * 16 + lq) * 4 + wcol] = s0;
            ssq_s[(wrow * 32 + mt * 16 + lq + 8) * 4 + wcol] = s1;
        }
    }
    __syncthreads();
    if (tid < 128) {
        float v = ssq_s[tid * 4] + ssq_s[tid * 4 + 1] + ssq_s[tid * 4 + 2] + ssq_s[tid * 4 + 3];
        inv_s[tid] = (v > 0.f) ? rsqrtf(v) : 1.0f;
    }
    __syncthreads();

#pragma unroll
    for (int mt = 0; mt < MT; mt++) {
        const int r0 = wrow * 32 + mt * 16 + lq;
        const float i0 = inv_s[r0], i1 = inv_s[r0 + 8];
#pragma unroll
        for (int nt = 0; nt < NT; nt++) {
            const int col = wcol * 64 + nt * 8 + 2 * lr;
            *(float2*)(out + (size_t)(rb + r0) * DF + col) =
                make_float2(acc[mt][nt][0] * i0, acc[mt][nt][1] * i0);
            *(float2*)(out + (size_t)(rb + r0 + 8) * DF + col) =
                make_float2(acc[mt][nt][2] * i1, acc[mt][nt][3] * i1);
        }
    }
}

// ---------------------------------------------------------------------------
// Gather 2: X2 = tf32round([H1[r] | mean_{10} H1[...]])  — 8 rows / 512 thr
// ---------------------------------------------------------------------------
__global__ void __launch_bounds__(512) gather2_kernel() {
    const int g = threadIdx.x >> 6, c = threadIdx.x & 63;
    const int r = blockIdx.x * 8 + g;
    const float4* H = (const float4*)g_H1;
    float4* X2v = (float4*)g_X2;
    X2v[(size_t)r * 128 + c] = tf32r4(H[(size_t)r * 64 + c]);
    float4 s = make_float4(0.f, 0.f, 0.f, 0.f);
#pragma unroll
    for (int j = 0; j < S1; j++) {
        float4 v = H[(size_t)(BQ + r * S1 + j) * 64 + c];
        s.x += v.x; s.y += v.y; s.z += v.z; s.w += v.w;
    }
    const float is = 1.0f / S1;
    s.x *= is; s.y *= is; s.z *= is; s.w *= is;
    X2v[(size_t)r * 128 + 64 + c] = tf32r4(s);
}

// ---------------------------------------------------------------------------
// GEMM2 split-K, SINGLE stage, 512 threads: 32 rows x 256 cols x K=128.
// Warp grid 2x8 (wrow 0..1 x 16 rows, wcol 0..7 x 32 cols; MT=1, NT=4).
// ---------------------------------------------------------------------------
__global__ void __launch_bounds__(512, 1)
gemm2_splitk(const float* __restrict__ X, const float* __restrict__ W) {
    constexpr int BM = 32, BN = 256, NT = 4;

    extern __shared__ float sm[];
    float* As = sm;                    // [BM][A2STR]
    float* Bs = sm + BM * A2STR;       // [BN][A2STR]

    const int tid  = threadIdx.x;
    const int wid  = tid >> 5;
    const int lane = tid & 31;
    const int wrow = wid >> 3;         // 0..1
    const int wcol = wid & 7;          // 0..7
    const int rb   = blockIdx.x * BM;
    const int kbase = blockIdx.y * 128;
    const int lq   = lane >> 2;
    const int lr   = lane & 3;

    const uint32_t as_b = smem_u32(As);
    const uint32_t bs_b = smem_u32(Bs);

    // stage everything: A = 32x32 float4, B = 256x32 float4
#pragma unroll
    for (int i = tid; i < BM * 32; i += 512) {
        int r = i >> 5, q = i & 31;
        cpa16(as_b + (uint32_t)(r * A2STR + q * 4) * 4,
              X + (size_t)(rb + r) * KDIM + kbase + q * 4);
    }
#pragma unroll
    for (int i = tid; i < BN * 32; i += 512) {
        int n = i >> 5, q = i & 31;
        cpa16(bs_b + (uint32_t)(n * A2STR + q * 4) * 4,
              W + (size_t)n * KDIM + kbase + q * 4);
    }
    CP_COMMIT();

    float acc[NT][4];
#pragma unroll
    for (int j = 0; j < NT; j++)
#pragma unroll
        for (int q = 0; q < 4; q++) acc[j][q] = 0.f;

    CP_WAIT(0);
    __syncthreads();

#pragma unroll
    for (int ks = 0; ks < 16; ks++) {
        const int k0 = ks * 8;
        uint32_t af[4];
        {
            const uint32_t* ap = (const uint32_t*)(As
                + (size_t)(wrow * 16 + lq) * A2STR + k0 + lr);
            af[0] = ap[0];
            af[1] = ap[8 * A2STR];
            af[2] = ap[4];
            af[3] = ap[8 * A2STR + 4];
        }
        uint32_t bf[NT][2];
#pragma unroll
        for (int nt = 0; nt < NT; nt++) {
            const uint32_t* bp = (const uint32_t*)(Bs
                + (size_t)(wcol * 32 + nt * 8 + lq) * A2STR + k0 + lr);
            bf[nt][0] = bp[0];
            bf[nt][1] = bp[4];
        }
#pragma unroll
        for (int nt = 0; nt < NT; nt++)
            mma_tf32(acc[nt], af, bf[nt]);
    }

    float* P = g_P[blockIdx.y];
    const int r0 = wrow * 16 + lq;
#pragma unroll
    for (int nt = 0; nt < NT; nt++) {
        const int col = wcol * 32 + nt * 8 + 2 * lr;
        *(float2*)(P + (size_t)(rb + r0) * DF + col)     = make_float2(acc[nt][0], acc[nt][1]);
        *(float2*)(P + (size_t)(rb + r0 + 8) * DF + col) = make_float2(acc[nt][2], acc[nt][3]);
    }
}

// ---------------------------------------------------------------------------
// Combine: sum 4 partials + bias + relu + L2 norm -> final output.
// ---------------------------------------------------------------------------
__global__ void __launch_bounds__(512) combine_kernel(const float* __restrict__ bias,
                                                      float* __restrict__ out) {
    const int wid = threadIdx.x >> 5, lane = threadIdx.x & 31;
    const int row = blockIdx.x * 16 + wid;

    const float4* P0 = (const float4*)(g_P[0] + (size_t)row * DF);
    const float4* P1 = (const float4*)(g_P[1] + (size_t)row * DF);
    const float4* P2 = (const float4*)(g_P[2] + (size_t)row * DF);
    const float4* P3 = (const float4*)(g_P[3] + (size_t)row * DF);
    const float4* Bv = (const float4*)bias;

    float4 v[2];
    float ssq = 0.f;
#pragma unroll
    for (int t = 0; t < 2; t++) {
        const int idx = lane + t * 32;
        float4 a = P0[idx], b = P1[idx], c = P2[idx], d = P3[idx], e = Bv[idx];
        float4 r;
        r.x = fmaxf(a.x + b.x + c.x + d.x + e.x, 0.f);
        r.y = fmaxf(a.y + b.y + c.y + d.y + e.y, 0.f);
        r.z = fmaxf(a.z + b.z + c.z + d.z + e.z, 0.f);
        r.w = fmaxf(a.w + b.w + c.w + d.w + e.w, 0.f);
        ssq += r.x * r.x + r.y * r.y + r.z * r.z + r.w * r.w;
        v[t] = r;
    }
#pragma unroll
    for (int o = 16; o > 0; o >>= 1)
        ssq += __shfl_xor_sync(0xffffffffu, ssq, o);
    const float inv = (ssq > 0.f) ? rsqrtf(ssq) : 1.0f;

    float4* dst = (float4*)(out + (size_t)row * DF);
#pragma unroll
    for (int t = 0; t < 2; t++) {
        float4 r = v[t];
        r.x *= inv; r.y *= inv; r.z *= inv; r.w *= inv;
        dst[lane + t * 32] = r;
    }
}

// ---------------------------------------------------------------------------
extern "C" void kernel_launch(void* const* d_in, const int* in_sizes, int n_in,
                              void* d_out, int out_size) {
    const float* features = (const float*)d_in[0];
    const float* W0       = (const float*)d_in[1];
    const float* b0       = (const float*)d_in[2];
    const float* W1       = (const float*)d_in[3];
    const float* b1       = (const float*)d_in[4];
    const int*   nodes2   = (const int*)d_in[5];
    const int*   neigh2   = (const int*)d_in[6];
    const int*   neigh1   = (const int*)d_in[7];
    float*       outp     = (float*)d_out;

    float *x1, *h1, *x2, *w0r, *w1r;
    cudaGetSymbolAddress((void**)&x1, g_X1);
    cudaGetSymbolAddress((void**)&h1, g_H1);
    cudaGetSymbolAddress((void**)&x2, g_X2);
    cudaGetSymbolAddress((void**)&w0r, g_W0r);
    cudaGetSymbolAddress((void**)&w1r, g_W1r);

    constexpr int SM1 = 3 * (128 + 256) * ASTR * 4;    // 165888
    constexpr int SM2 = (32 + 256) * A2STR * 4;        // 152064
    static bool attr_done = false;
    if (!attr_done) {
        cudaFuncSetAttribute((const void*)gemm1_kernel,
                             cudaFuncAttributeMaxDynamicSharedMemorySize, SM1);
        cudaFuncSetAttribute((const void*)gemm2_splitk,
                             cudaFuncAttributeMaxDynamicSharedMemorySize, SM2);
        attr_done = true;
    }

    prep_gather1<<<512 + N1 / 4, 256>>>((const float4*)features, W0, W1,
                                        nodes2, neigh2, neigh1);
    gemm1_kernel<<<NTILE, 512, SM1>>>(x1, w0r, b0, h1);
    gather2_kernel<<<BQ / 8, 512>>>();
    gemm2_splitk<<<dim3(BQ / 32, 4), 512, SM2>>>(x2, w1r);
    combine_kernel<<<BQ / 16, 512>>>(b1, outp);
}